// round 7
// baseline (speedup 1.0000x reference)
#include <cuda_runtime.h>
#include <cstdint>

#define M_TOTAL 16384
#define K_DIM   2048
#define E_DIM   64
#define TOPK    8

#define BM    128
#define BK    32
#define NTILE (K_DIM / BK)   // 64
#define NTHR  512
#define LSTR  68             // epilogue logits row stride (floats)

// One-time W transpose scratch: Wt[k][e]
__device__ float Wt_g[(size_t)K_DIM * E_DIM];

__global__ void transpose_w(const float* __restrict__ W, float* __restrict__ Wt) {
    int t = blockIdx.x * blockDim.x + threadIdx.x;   // 131072
    int e = t >> 11;
    int k = t & (K_DIM - 1);
    Wt[(size_t)k * E_DIM + e] = W[(size_t)e * K_DIM + k];
}

// Packed fp32x2 FMA; per-lane rounding identical to scalar fmaf.
__device__ __forceinline__ float2 ffma2(float2 a, float2 b, float2 c) {
    float2 d;
    asm("fma.rn.f32x2 %0, %1, %2, %3;"
        : "=l"(reinterpret_cast<unsigned long long&>(d))
        : "l"(reinterpret_cast<unsigned long long&>(a)),
          "l"(reinterpret_cast<unsigned long long&>(b)),
          "l"(reinterpret_cast<unsigned long long&>(c)));
    return d;
}

// Fused logits GEMM + top-8 + softmax. 512 threads = 16 warps (4 warps/SMSP
// for latency hiding — round 6 was latency-bound at 2/SMSP).
// Warp w: experts e0 = (w&3)*16 (uniform across lanes -> broadcast b loads),
//         m row   = (w>>2)*32 + lane (one m per lane).
// a_sm k-major [BK][BM], XOR swizzle col = m ^ (4*(k>>2)): STS and LDS both
// conflict-free. Sequential ascending-k FMA chain per (m,e) -> bit-identical
// results to rounds 3/6.
__global__ __launch_bounds__(NTHR, 1)
void router_fused(const float* __restrict__ X, const float* __restrict__ Wt,
                  float* __restrict__ logits,
                  float* __restrict__ wout, float* __restrict__ eout) {
    __shared__ float smem[BM * LSTR];          // 34.8 KB (epilogue size; mainloop uses 24 KB)
    float* a_sm = smem;                        // [BK][BM] swizzled (4096 floats)
    float* b_sm = smem + BK * BM;              // [BK][E_DIM] (2048 floats)

    const int tid  = threadIdx.x;
    const int w    = tid >> 5;
    const int lane = tid & 31;
    const int e0   = (w & 3) * 16;
    const int mrow = (w >> 2) * 32 + lane;
    const int m0   = blockIdx.x * BM;

    float2 acc[8];
    #pragma unroll
    for (int j = 0; j < 8; j++) acc[j] = make_float2(0.f, 0.f);

    // prefetch regs: a tile = 1024 float4 -> 2/thread; b tile = 512 float4 -> 1/thread
    float4 pa[2];
    float4 pb;
    int am[2], aq[2];
    #pragma unroll
    for (int i = 0; i < 2; i++) { int f = tid + i * NTHR; am[i] = f >> 3; aq[i] = f & 7; }

    #pragma unroll
    for (int i = 0; i < 2; i++)
        pa[i] = *reinterpret_cast<const float4*>(&X[(size_t)(m0 + am[i]) * K_DIM + aq[i] * 4]);
    pb = reinterpret_cast<const float4*>(Wt)[tid];

    for (int t = 0; t < NTILE; t++) {
        // ---- stage a (k-major, swizzled) ----
        #pragma unroll
        for (int i = 0; i < 2; i++) {
            int q   = aq[i];
            int col = am[i] ^ (4 * q);
            float vs[4] = {pa[i].x, pa[i].y, pa[i].z, pa[i].w};
            #pragma unroll
            for (int j = 0; j < 4; j++)
                a_sm[(4 * q + j) * BM + col] = vs[j];
        }
        // ---- stage b ----
        reinterpret_cast<float4*>(b_sm)[tid] = pb;
        __syncthreads();

        // ---- prefetch next tile ----
        if (t + 1 < NTILE) {
            int kn = (t + 1) * BK;
            #pragma unroll
            for (int i = 0; i < 2; i++)
                pa[i] = *reinterpret_cast<const float4*>(
                    &X[(size_t)(m0 + am[i]) * K_DIM + kn + aq[i] * 4]);
            pb = reinterpret_cast<const float4*>(&Wt[(size_t)kn * E_DIM])[tid];
        }

        // ---- mainloop ----
        #pragma unroll
        for (int kk = 0; kk < BK; kk++) {
            const int sw = 4 * (kk >> 2);
            float4 b4[4];
            #pragma unroll
            for (int j = 0; j < 4; j++)
                b4[j] = *reinterpret_cast<const float4*>(&b_sm[kk * E_DIM + e0 + 4 * j]);
            float a1 = a_sm[kk * BM + (mrow ^ sw)];
            float2 ap = make_float2(a1, a1);
            #pragma unroll
            for (int j = 0; j < 4; j++) {
                float2 blo = make_float2(b4[j].x, b4[j].y);
                float2 bhi = make_float2(b4[j].z, b4[j].w);
                acc[2 * j]     = ffma2(ap, blo, acc[2 * j]);
                acc[2 * j + 1] = ffma2(ap, bhi, acc[2 * j + 1]);
            }
        }
        __syncthreads();
    }

    // ---- epilogue: logits to global + stage rows in smem for topk ----
    #pragma unroll
    for (int j = 0; j < 4; j++) {
        float4 v = make_float4(acc[2 * j].x, acc[2 * j].y,
                               acc[2 * j + 1].x, acc[2 * j + 1].y);
        *reinterpret_cast<float4*>(&logits[(size_t)(m0 + mrow) * E_DIM + e0 + 4 * j]) = v;
        *reinterpret_cast<float4*>(&smem[mrow * LSTR + e0 + 4 * j]) = v;
    }
    __syncthreads();

    // ---- top-8 + softmax: one thread per token (threads 0..127) ----
    if (tid < BM) {
        const float* row = &smem[tid * LSTR];
        float tv[TOPK];
        int   ti[TOPK];
        #pragma unroll
        for (int i = 0; i < TOPK; i++) { tv[i] = -3.4e38f; ti[i] = 0; }

        #pragma unroll
        for (int q = 0; q < E_DIM / 4; q++) {
            float4 v4 = *reinterpret_cast<const float4*>(&row[q * 4]);
            float vs[4] = {v4.x, v4.y, v4.z, v4.w};
            #pragma unroll
            for (int u = 0; u < 4; u++) {
                float v = vs[u];
                int   e = q * 4 + u;
                if (v > tv[TOPK - 1]) {
                    tv[TOPK - 1] = v; ti[TOPK - 1] = e;
                    #pragma unroll
                    for (int j = TOPK - 1; j > 0; j--) {
                        if (tv[j] > tv[j - 1]) {   // strict: ties keep earlier index
                            float tf = tv[j]; tv[j] = tv[j - 1]; tv[j - 1] = tf;
                            int   tx = ti[j]; ti[j] = ti[j - 1]; ti[j - 1] = tx;
                        }
                    }
                }
            }
        }

        float mx = tv[0];
        float ev[TOPK], ssum = 0.f;
        #pragma unroll
        for (int i = 0; i < TOPK; i++) { ev[i] = __expf(tv[i] - mx); ssum += ev[i]; }
        float inv = 1.f / ssum;
        size_t tok = (size_t)(m0 + tid);
        #pragma unroll
        for (int i = 0; i < TOPK; i++) {
            wout[tok * TOPK + i] = ev[i] * inv;
            eout[tok * TOPK + i] = (float)ti[i];
        }
    }
}

extern "C" void kernel_launch(void* const* d_in, const int* in_sizes, int n_in,
                              void* d_out, int out_size) {
    const float* X = (const float*)d_in[0];   // [4,4096,2048] fp32
    const float* W = (const float*)d_in[1];   // [64,2048]     fp32

    float* out    = (float*)d_out;
    float* logits = out;                                   // 16384*64
    float* wts    = out + (size_t)M_TOTAL * E_DIM;         // 16384*8
    float* exps   = wts + (size_t)M_TOTAL * TOPK;          // 16384*8

    float* Wt;
    cudaGetSymbolAddress((void**)&Wt, Wt_g);

    transpose_w<<<(K_DIM * E_DIM) / 256, 256>>>(W, Wt);
    router_fused<<<M_TOTAL / BM, NTHR>>>(X, Wt, logits, wts, exps);
}

// round 8
// speedup vs baseline: 1.4025x; 1.4025x over previous
#include <cuda_runtime.h>
#include <cstdint>

#define M_TOTAL 16384
#define K_DIM   2048
#define E_DIM   64
#define TOPK    8

#define BM    128
#define BK    32
#define NTILE (K_DIM / BK)   // 64
#define NTHR  256
#define LSTR  68             // epilogue logits row stride (floats)
#define BUFSZ (BK * BM + BK * E_DIM)   // 6144 floats per buffer

// One-time W transpose scratch: Wt[k][e]
__device__ float Wt_g[(size_t)K_DIM * E_DIM];

__global__ void transpose_w(const float* __restrict__ W, float* __restrict__ Wt) {
    int t = blockIdx.x * blockDim.x + threadIdx.x;   // 131072
    int e = t >> 11;
    int k = t & (K_DIM - 1);
    Wt[(size_t)k * E_DIM + e] = W[(size_t)e * K_DIM + k];
}

// Packed fp32x2 FMA; per-lane rounding identical to scalar fmaf.
__device__ __forceinline__ float2 ffma2(float2 a, float2 b, float2 c) {
    float2 d;
    asm("fma.rn.f32x2 %0, %1, %2, %3;"
        : "=l"(reinterpret_cast<unsigned long long&>(d))
        : "l"(reinterpret_cast<unsigned long long&>(a)),
          "l"(reinterpret_cast<unsigned long long&>(b)),
          "l"(reinterpret_cast<unsigned long long&>(c)));
    return d;
}

__device__ __forceinline__ void cp_async16(uint32_t dst_smem, const void* src) {
    asm volatile("cp.async.ca.shared.global [%0], [%1], 16;"
                 :: "r"(dst_smem), "l"(src));
}
__device__ __forceinline__ void cp_async_commit() {
    asm volatile("cp.async.commit_group;");
}
__device__ __forceinline__ void cp_async_wait0() {
    asm volatile("cp.async.wait_group 0;");
}

// Fused logits GEMM + top-8 + softmax. Round-6 geometry (the best measured:
// warp = 16 experts x 2 m-rows; uniform LDS.128 for b, coalesced LDS.32 for a,
// XOR-swizzled k-major a) + DOUBLE-BUFFERED smem: one barrier per tile, b tile
// via cp.async, a staging overlapped with the mainloop.
// Sequential ascending-k FMA chain per (m,e) -> bit-identical to rounds 3/6.
__global__ __launch_bounds__(NTHR, 1)
void router_fused(const float* __restrict__ X, const float* __restrict__ Wt,
                  float* __restrict__ logits,
                  float* __restrict__ wout, float* __restrict__ eout) {
    __shared__ float smem[2 * BUFSZ];          // 12288 floats = 48 KB static
    // buffer layout: a(buf) = smem + buf*BUFSZ ([BK][BM] swizzled),
    //                b(buf) = a(buf) + BK*BM   ([BK][E_DIM])

    const int tid  = threadIdx.x;
    const int w    = tid >> 5;
    const int lane = tid & 31;
    const int e0   = (w & 3) * 16;
    const int m1   = (w >> 2) * 64 + lane;
    const int m2   = m1 + 32;
    const int m0   = blockIdx.x * BM;

    const uint32_t smem_u32 = (uint32_t)__cvta_generic_to_shared(smem);

    float2 acc[2][8];
    #pragma unroll
    for (int r = 0; r < 2; r++)
        #pragma unroll
        for (int j = 0; j < 8; j++) acc[r][j] = make_float2(0.f, 0.f);

    // a-tile staging map: 1024 float4 -> 4 per thread
    float4 pa[4];
    int am[4], aq[4];
    #pragma unroll
    for (int i = 0; i < 4; i++) { int f = tid + i * NTHR; am[i] = f >> 3; aq[i] = f & 7; }

    // ---- preload tile 0 ----
    {
        // b tile 0 via cp.async: 512 float4, 2 per thread
        uint32_t b0 = smem_u32 + (uint32_t)(BK * BM) * 4u;
        cp_async16(b0 + tid * 16u,         &Wt[(size_t)tid * 4]);
        cp_async16(b0 + (tid + 256) * 16u, &Wt[(size_t)(tid + 256) * 4]);
        cp_async_commit();
        // a tile 0: LDG -> swizzled STS
        #pragma unroll
        for (int i = 0; i < 4; i++) {
            float4 v = *reinterpret_cast<const float4*>(
                &X[(size_t)(m0 + am[i]) * K_DIM + aq[i] * 4]);
            int q = aq[i], col = am[i] ^ (4 * q);
            float vs[4] = {v.x, v.y, v.z, v.w};
            #pragma unroll
            for (int j = 0; j < 4; j++)
                smem[(4 * q + j) * BM + col] = vs[j];
        }
        cp_async_wait0();
    }
    __syncthreads();

    for (int t = 0; t < NTILE; t++) {
        const int cur = t & 1;
        const float* a_sm = smem + cur * BUFSZ;
        const float* b_sm = a_sm + BK * BM;
        float* a_nx = smem + (cur ^ 1) * BUFSZ;

        const bool has_next = (t + 1 < NTILE);
        // ---- issue next-tile loads early ----
        if (has_next) {
            int kn = (t + 1) * BK;
            uint32_t bdst = smem_u32 + (uint32_t)((cur ^ 1) * BUFSZ + BK * BM) * 4u;
            const float* bsrc = &Wt[(size_t)kn * E_DIM];
            cp_async16(bdst + tid * 16u,         bsrc + (size_t)tid * 4);
            cp_async16(bdst + (tid + 256) * 16u, bsrc + (size_t)(tid + 256) * 4);
            cp_async_commit();
            #pragma unroll
            for (int i = 0; i < 4; i++)
                pa[i] = *reinterpret_cast<const float4*>(
                    &X[(size_t)(m0 + am[i]) * K_DIM + kn + aq[i] * 4]);
        }

        // ---- mainloop over current buffer ----
        #pragma unroll
        for (int kk = 0; kk < BK; kk++) {
            const int sw = 4 * (kk >> 2);
            float4 b4[4];
            #pragma unroll
            for (int j = 0; j < 4; j++)
                b4[j] = *reinterpret_cast<const float4*>(&b_sm[kk * E_DIM + e0 + 4 * j]);
            float a1 = a_sm[kk * BM + (m1 ^ sw)];
            float a2 = a_sm[kk * BM + (m2 ^ sw)];
            float2 ap1 = make_float2(a1, a1);
            float2 ap2 = make_float2(a2, a2);
            #pragma unroll
            for (int j = 0; j < 4; j++) {
                float2 blo = make_float2(b4[j].x, b4[j].y);
                float2 bhi = make_float2(b4[j].z, b4[j].w);
                acc[0][2 * j]     = ffma2(ap1, blo, acc[0][2 * j]);
                acc[0][2 * j + 1] = ffma2(ap1, bhi, acc[0][2 * j + 1]);
                acc[1][2 * j]     = ffma2(ap2, blo, acc[1][2 * j]);
                acc[1][2 * j + 1] = ffma2(ap2, bhi, acc[1][2 * j + 1]);
            }
        }

        // ---- stage next a into alternate buffer ----
        if (has_next) {
            #pragma unroll
            for (int i = 0; i < 4; i++) {
                int q = aq[i], col = am[i] ^ (4 * q);
                float vs[4] = {pa[i].x, pa[i].y, pa[i].z, pa[i].w};
                #pragma unroll
                for (int j = 0; j < 4; j++)
                    a_nx[(4 * q + j) * BM + col] = vs[j];
            }
            cp_async_wait0();
        }
        __syncthreads();
    }

    // ---- epilogue: logits to global + stage rows in smem for topk ----
    #pragma unroll
    for (int r = 0; r < 2; r++) {
        int m = r ? m2 : m1;
        #pragma unroll
        for (int j = 0; j < 4; j++) {
            float4 v = make_float4(acc[r][2 * j].x, acc[r][2 * j].y,
                                   acc[r][2 * j + 1].x, acc[r][2 * j + 1].y);
            *reinterpret_cast<float4*>(&logits[(size_t)(m0 + m) * E_DIM + e0 + 4 * j]) = v;
            *reinterpret_cast<float4*>(&smem[m * LSTR + e0 + 4 * j]) = v;
        }
    }
    __syncthreads();

    // ---- top-8 + softmax: one thread per token (threads 0..127) ----
    if (tid < BM) {
        const float* row = &smem[tid * LSTR];
        float tv[TOPK];
        int   ti[TOPK];
        #pragma unroll
        for (int i = 0; i < TOPK; i++) { tv[i] = -3.4e38f; ti[i] = 0; }

        #pragma unroll
        for (int q = 0; q < E_DIM / 4; q++) {
            float4 v4 = *reinterpret_cast<const float4*>(&row[q * 4]);
            float vs[4] = {v4.x, v4.y, v4.z, v4.w};
            #pragma unroll
            for (int u = 0; u < 4; u++) {
                float v = vs[u];
                int   e = q * 4 + u;
                if (v > tv[TOPK - 1]) {
                    tv[TOPK - 1] = v; ti[TOPK - 1] = e;
                    #pragma unroll
                    for (int j = TOPK - 1; j > 0; j--) {
                        if (tv[j] > tv[j - 1]) {   // strict: ties keep earlier index
                            float tf = tv[j]; tv[j] = tv[j - 1]; tv[j - 1] = tf;
                            int   tx = ti[j]; ti[j] = ti[j - 1]; ti[j - 1] = tx;
                        }
                    }
                }
            }
        }

        float mx = tv[0];
        float ev[TOPK], ssum = 0.f;
        #pragma unroll
        for (int i = 0; i < TOPK; i++) { ev[i] = __expf(tv[i] - mx); ssum += ev[i]; }
        float inv = 1.f / ssum;
        size_t tok = (size_t)(m0 + tid);
        #pragma unroll
        for (int i = 0; i < TOPK; i++) {
            wout[tok * TOPK + i] = ev[i] * inv;
            eout[tok * TOPK + i] = (float)ti[i];
        }
    }
}

extern "C" void kernel_launch(void* const* d_in, const int* in_sizes, int n_in,
                              void* d_out, int out_size) {
    const float* X = (const float*)d_in[0];   // [4,4096,2048] fp32
    const float* W = (const float*)d_in[1];   // [64,2048]     fp32

    float* out    = (float*)d_out;
    float* logits = out;                                   // 16384*64
    float* wts    = out + (size_t)M_TOTAL * E_DIM;         // 16384*8
    float* exps   = wts + (size_t)M_TOTAL * TOPK;          // 16384*8

    float* Wt;
    cudaGetSymbolAddress((void**)&Wt, Wt_g);

    transpose_w<<<(K_DIM * E_DIM) / 256, 256>>>(W, Wt);
    router_fused<<<M_TOTAL / BM, NTHR>>>(X, Wt, logits, wts, exps);
}

// round 9
// speedup vs baseline: 1.4057x; 1.0023x over previous
#include <cuda_runtime.h>
#include <cstdint>

#define M_TOTAL 16384
#define K_DIM   2048
#define E_DIM   64
#define TOPK    8

#define BM    128
#define BK    32
#define NTILE (K_DIM / BK)   // 64
#define NTHR  256
#define LSTR  68             // epilogue logits row stride (floats)
#define BUFSZ (BK * BM + BK * E_DIM)   // 6144 floats per buffer

// One-time W transpose scratch: Wt[k][e]
__device__ float Wt_g[(size_t)K_DIM * E_DIM];

__global__ void transpose_w(const float* __restrict__ W, float* __restrict__ Wt) {
    int t = blockIdx.x * blockDim.x + threadIdx.x;   // 131072
    int e = t >> 11;
    int k = t & (K_DIM - 1);
    Wt[(size_t)k * E_DIM + e] = W[(size_t)e * K_DIM + k];
}

// Packed fp32x2 FMA; per-lane rounding identical to scalar fmaf.
__device__ __forceinline__ float2 ffma2(float2 a, float2 b, float2 c) {
    float2 d;
    asm("fma.rn.f32x2 %0, %1, %2, %3;"
        : "=l"(reinterpret_cast<unsigned long long&>(d))
        : "l"(reinterpret_cast<unsigned long long&>(a)),
          "l"(reinterpret_cast<unsigned long long&>(b)),
          "l"(reinterpret_cast<unsigned long long&>(c)));
    return d;
}

__device__ __forceinline__ void cp_async16(uint32_t dst_smem, const void* src) {
    asm volatile("cp.async.ca.shared.global [%0], [%1], 16;"
                 :: "r"(dst_smem), "l"(src));
}
__device__ __forceinline__ void cp_async_commit() {
    asm volatile("cp.async.commit_group;");
}
__device__ __forceinline__ void cp_async_wait0() {
    asm volatile("cp.async.wait_group 0;");
}

// Fused logits GEMM + top-8 + softmax. Round-8 structure (warp = 16 experts x
// 2 m-rows, uniform LDS.128 b / coalesced LDS.32 a, XOR swizzle, double
// buffer, cp.async b) + EXPLICIT one-kk register pipelining of smem loads so
// the 29-cyc LDS latency is covered by kk's FFMA stream instead of stalling.
// Sequential ascending-k FMA chain per (m,e) -> bit-identical to rounds 3/6/8.
__global__ __launch_bounds__(NTHR, 1)
void router_fused(const float* __restrict__ X, const float* __restrict__ Wt,
                  float* __restrict__ logits,
                  float* __restrict__ wout, float* __restrict__ eout) {
    __shared__ float smem[2 * BUFSZ];          // 48 KB static

    const int tid  = threadIdx.x;
    const int w    = tid >> 5;
    const int lane = tid & 31;
    const int e0   = (w & 3) * 16;
    const int m1   = (w >> 2) * 64 + lane;
    const int m2   = m1 + 32;
    const int m0   = blockIdx.x * BM;

    const uint32_t smem_u32 = (uint32_t)__cvta_generic_to_shared(smem);

    float2 acc[2][8];
    #pragma unroll
    for (int r = 0; r < 2; r++)
        #pragma unroll
        for (int j = 0; j < 8; j++) acc[r][j] = make_float2(0.f, 0.f);

    // a-tile staging map: 1024 float4 -> 4 per thread
    float4 pa[4];
    int am[4], aq[4];
    #pragma unroll
    for (int i = 0; i < 4; i++) { int f = tid + i * NTHR; am[i] = f >> 3; aq[i] = f & 7; }

    // ---- preload tile 0 ----
    {
        uint32_t b0 = smem_u32 + (uint32_t)(BK * BM) * 4u;
        cp_async16(b0 + tid * 16u,         &Wt[(size_t)tid * 4]);
        cp_async16(b0 + (tid + 256) * 16u, &Wt[(size_t)(tid + 256) * 4]);
        cp_async_commit();
        #pragma unroll
        for (int i = 0; i < 4; i++) {
            float4 v = *reinterpret_cast<const float4*>(
                &X[(size_t)(m0 + am[i]) * K_DIM + aq[i] * 4]);
            int q = aq[i], col = am[i] ^ (4 * q);
            float vs[4] = {v.x, v.y, v.z, v.w};
            #pragma unroll
            for (int j = 0; j < 4; j++)
                smem[(4 * q + j) * BM + col] = vs[j];
        }
        cp_async_wait0();
    }
    __syncthreads();

    for (int t = 0; t < NTILE; t++) {
        const int cur = t & 1;
        const float* a_sm = smem + cur * BUFSZ;
        const float* b_sm = a_sm + BK * BM;
        float* a_nx = smem + (cur ^ 1) * BUFSZ;

        const bool has_next = (t + 1 < NTILE);
        // ---- issue next-tile global loads early ----
        if (has_next) {
            int kn = (t + 1) * BK;
            uint32_t bdst = smem_u32 + (uint32_t)((cur ^ 1) * BUFSZ + BK * BM) * 4u;
            const float* bsrc = &Wt[(size_t)kn * E_DIM];
            cp_async16(bdst + tid * 16u,         bsrc + (size_t)tid * 4);
            cp_async16(bdst + (tid + 256) * 16u, bsrc + (size_t)(tid + 256) * 4);
            cp_async_commit();
            #pragma unroll
            for (int i = 0; i < 4; i++)
                pa[i] = *reinterpret_cast<const float4*>(
                    &X[(size_t)(m0 + am[i]) * K_DIM + kn + aq[i] * 4]);
        }

        // ---- mainloop, smem loads pipelined one kk ahead ----
        float4 nb[4];
        float  na1, na2;
        {   // prologue: kk = 0
            #pragma unroll
            for (int j = 0; j < 4; j++)
                nb[j] = *reinterpret_cast<const float4*>(&b_sm[e0 + 4 * j]);
            na1 = a_sm[m1];
            na2 = a_sm[m2];
        }
        #pragma unroll
        for (int kk = 0; kk < BK; kk++) {
            float4 cb[4];
            #pragma unroll
            for (int j = 0; j < 4; j++) cb[j] = nb[j];
            float ca1 = na1, ca2 = na2;

            if (kk + 1 < BK) {
                const int kn = kk + 1;
                const int sw = 4 * (kn >> 2);
                #pragma unroll
                for (int j = 0; j < 4; j++)
                    nb[j] = *reinterpret_cast<const float4*>(&b_sm[kn * E_DIM + e0 + 4 * j]);
                na1 = a_sm[kn * BM + (m1 ^ sw)];
                na2 = a_sm[kn * BM + (m2 ^ sw)];
            }

            float2 ap1 = make_float2(ca1, ca1);
            float2 ap2 = make_float2(ca2, ca2);
            #pragma unroll
            for (int j = 0; j < 4; j++) {
                float2 blo = make_float2(cb[j].x, cb[j].y);
                float2 bhi = make_float2(cb[j].z, cb[j].w);
                acc[0][2 * j]     = ffma2(ap1, blo, acc[0][2 * j]);
                acc[0][2 * j + 1] = ffma2(ap1, bhi, acc[0][2 * j + 1]);
                acc[1][2 * j]     = ffma2(ap2, blo, acc[1][2 * j]);
                acc[1][2 * j + 1] = ffma2(ap2, bhi, acc[1][2 * j + 1]);
            }
        }

        // ---- stage next a into alternate buffer ----
        if (has_next) {
            #pragma unroll
            for (int i = 0; i < 4; i++) {
                int q = aq[i], col = am[i] ^ (4 * q);
                float vs[4] = {pa[i].x, pa[i].y, pa[i].z, pa[i].w};
                #pragma unroll
                for (int j = 0; j < 4; j++)
                    a_nx[(4 * q + j) * BM + col] = vs[j];
            }
            cp_async_wait0();
        }
        __syncthreads();
    }

    // ---- epilogue: logits to global + stage rows in smem for topk ----
    #pragma unroll
    for (int r = 0; r < 2; r++) {
        int m = r ? m2 : m1;
        #pragma unroll
        for (int j = 0; j < 4; j++) {
            float4 v = make_float4(acc[r][2 * j].x, acc[r][2 * j].y,
                                   acc[r][2 * j + 1].x, acc[r][2 * j + 1].y);
            *reinterpret_cast<float4*>(&logits[(size_t)(m0 + m) * E_DIM + e0 + 4 * j]) = v;
            *reinterpret_cast<float4*>(&smem[m * LSTR + e0 + 4 * j]) = v;
        }
    }
    __syncthreads();

    // ---- top-8 + softmax: one thread per token (threads 0..127) ----
    if (tid < BM) {
        const float* row = &smem[tid * LSTR];
        float tv[TOPK];
        int   ti[TOPK];
        #pragma unroll
        for (int i = 0; i < TOPK; i++) { tv[i] = -3.4e38f; ti[i] = 0; }

        #pragma unroll
        for (int q = 0; q < E_DIM / 4; q++) {
            float4 v4 = *reinterpret_cast<const float4*>(&row[q * 4]);
            float vs[4] = {v4.x, v4.y, v4.z, v4.w};
            #pragma unroll
            for (int u = 0; u < 4; u++) {
                float v = vs[u];
                int   e = q * 4 + u;
                if (v > tv[TOPK - 1]) {
                    tv[TOPK - 1] = v; ti[TOPK - 1] = e;
                    #pragma unroll
                    for (int j = TOPK - 1; j > 0; j--) {
                        if (tv[j] > tv[j - 1]) {   // strict: ties keep earlier index
                            float tf = tv[j]; tv[j] = tv[j - 1]; tv[j - 1] = tf;
                            int   tx = ti[j]; ti[j] = ti[j - 1]; ti[j - 1] = tx;
                        }
                    }
                }
            }
        }

        float mx = tv[0];
        float ev[TOPK], ssum = 0.f;
        #pragma unroll
        for (int i = 0; i < TOPK; i++) { ev[i] = __expf(tv[i] - mx); ssum += ev[i]; }
        float inv = 1.f / ssum;
        size_t tok = (size_t)(m0 + tid);
        #pragma unroll
        for (int i = 0; i < TOPK; i++) {
            wout[tok * TOPK + i] = ev[i] * inv;
            eout[tok * TOPK + i] = (float)ti[i];
        }
    }
}

extern "C" void kernel_launch(void* const* d_in, const int* in_sizes, int n_in,
                              void* d_out, int out_size) {
    const float* X = (const float*)d_in[0];   // [4,4096,2048] fp32
    const float* W = (const float*)d_in[1];   // [64,2048]     fp32

    float* out    = (float*)d_out;
    float* logits = out;                                   // 16384*64
    float* wts    = out + (size_t)M_TOTAL * E_DIM;         // 16384*8
    float* exps   = wts + (size_t)M_TOTAL * TOPK;          // 16384*8

    float* Wt;
    cudaGetSymbolAddress((void**)&Wt, Wt_g);

    transpose_w<<<(K_DIM * E_DIM) / 256, 256>>>(W, Wt);
    router_fused<<<M_TOTAL / BM, NTHR>>>(X, Wt, logits, wts, exps);
}

// round 10
// speedup vs baseline: 1.4089x; 1.0023x over previous
#include <cuda_runtime.h>
#include <cstdint>

#define M_TOTAL 16384
#define K_DIM   2048
#define E_DIM   64
#define TOPK    8

#define BM    128
#define BK    32
#define NTILE (K_DIM / BK)   // 64
#define NTHR  256
#define LSTR  68             // epilogue logits row stride (floats)
#define BUFSZ (BK * BM + BK * E_DIM)   // 6144 floats per buffer

// One-time W transpose scratch: Wt[k][e]
__device__ float Wt_g[(size_t)K_DIM * E_DIM];

__global__ void transpose_w(const float* __restrict__ W, float* __restrict__ Wt) {
    int t = blockIdx.x * blockDim.x + threadIdx.x;   // 131072
    int e = t >> 11;
    int k = t & (K_DIM - 1);
    Wt[(size_t)k * E_DIM + e] = W[(size_t)e * K_DIM + k];
}

// Packed fp32x2 FMA; per-lane rounding identical to scalar fmaf.
__device__ __forceinline__ float2 ffma2(float2 a, float2 b, float2 c) {
    float2 d;
    asm("fma.rn.f32x2 %0, %1, %2, %3;"
        : "=l"(reinterpret_cast<unsigned long long&>(d))
        : "l"(reinterpret_cast<unsigned long long&>(a)),
          "l"(reinterpret_cast<unsigned long long&>(b)),
          "l"(reinterpret_cast<unsigned long long&>(c)));
    return d;
}

__device__ __forceinline__ void cp_async16(uint32_t dst_smem, const void* src) {
    asm volatile("cp.async.ca.shared.global [%0], [%1], 16;"
                 :: "r"(dst_smem), "l"(src));
}
__device__ __forceinline__ void cp_async_commit() {
    asm volatile("cp.async.commit_group;");
}
__device__ __forceinline__ void cp_async_wait0() {
    asm volatile("cp.async.wait_group 0;");
}

// Fused logits GEMM + top-8 + softmax. Round-9 structure, with the inner FMA
// sequence SERPENTINE-ORDERED so every consecutive FFMA2 pair shares one
// 64-bit operand (a-pair or b-pair) -> SASS .reuse can drop one RF bank read
// per instruction, moving FFMA2 from rt~3 (3 distinct even/odd banks) toward
// rt~2. Same accumulators, same ascending-k chain per (m,e) -> bit-identical.
__global__ __launch_bounds__(NTHR, 1)
void router_fused(const float* __restrict__ X, const float* __restrict__ Wt,
                  float* __restrict__ logits,
                  float* __restrict__ wout, float* __restrict__ eout) {
    __shared__ float smem[2 * BUFSZ];          // 48 KB static

    const int tid  = threadIdx.x;
    const int w    = tid >> 5;
    const int lane = tid & 31;
    const int e0   = (w & 3) * 16;
    const int m1   = (w >> 2) * 64 + lane;
    const int m2   = m1 + 32;
    const int m0   = blockIdx.x * BM;

    const uint32_t smem_u32 = (uint32_t)__cvta_generic_to_shared(smem);

    float2 acc[2][8];
    #pragma unroll
    for (int r = 0; r < 2; r++)
        #pragma unroll
        for (int j = 0; j < 8; j++) acc[r][j] = make_float2(0.f, 0.f);

    // a-tile staging map: 1024 float4 -> 4 per thread
    float4 pa[4];
    int am[4], aq[4];
    #pragma unroll
    for (int i = 0; i < 4; i++) { int f = tid + i * NTHR; am[i] = f >> 3; aq[i] = f & 7; }

    // ---- preload tile 0 ----
    {
        uint32_t b0 = smem_u32 + (uint32_t)(BK * BM) * 4u;
        cp_async16(b0 + tid * 16u,         &Wt[(size_t)tid * 4]);
        cp_async16(b0 + (tid + 256) * 16u, &Wt[(size_t)(tid + 256) * 4]);
        cp_async_commit();
        #pragma unroll
        for (int i = 0; i < 4; i++) {
            float4 v = *reinterpret_cast<const float4*>(
                &X[(size_t)(m0 + am[i]) * K_DIM + aq[i] * 4]);
            int q = aq[i], col = am[i] ^ (4 * q);
            float vs[4] = {v.x, v.y, v.z, v.w};
            #pragma unroll
            for (int j = 0; j < 4; j++)
                smem[(4 * q + j) * BM + col] = vs[j];
        }
        cp_async_wait0();
    }
    __syncthreads();

    for (int t = 0; t < NTILE; t++) {
        const int cur = t & 1;
        const float* a_sm = smem + cur * BUFSZ;
        const float* b_sm = a_sm + BK * BM;
        float* a_nx = smem + (cur ^ 1) * BUFSZ;

        const bool has_next = (t + 1 < NTILE);
        if (has_next) {
            int kn = (t + 1) * BK;
            uint32_t bdst = smem_u32 + (uint32_t)((cur ^ 1) * BUFSZ + BK * BM) * 4u;
            const float* bsrc = &Wt[(size_t)kn * E_DIM];
            cp_async16(bdst + tid * 16u,         bsrc + (size_t)tid * 4);
            cp_async16(bdst + (tid + 256) * 16u, bsrc + (size_t)(tid + 256) * 4);
            cp_async_commit();
            #pragma unroll
            for (int i = 0; i < 4; i++)
                pa[i] = *reinterpret_cast<const float4*>(
                    &X[(size_t)(m0 + am[i]) * K_DIM + kn + aq[i] * 4]);
        }

        // ---- mainloop: serpentine FMA order for operand reuse ----
        #pragma unroll
        for (int kk = 0; kk < BK; kk++) {
            const int sw = 4 * (kk >> 2);
            float4 b4[4];
            #pragma unroll
            for (int j = 0; j < 4; j++)
                b4[j] = *reinterpret_cast<const float4*>(&b_sm[kk * E_DIM + e0 + 4 * j]);
            float a1 = a_sm[kk * BM + (m1 ^ sw)];
            float a2 = a_sm[kk * BM + (m2 ^ sw)];
            float2 ap1 = make_float2(a1, a1);
            float2 ap2 = make_float2(a2, a2);

            // Serpentine: consecutive FFMA2s always share exactly one operand.
            // j even:  (ap1,lo)(ap1,hi)(ap2,hi)(ap2,lo)
            // j odd :  (ap2,lo)(ap2,hi)(ap1,hi)(ap1,lo)
            // -> j-boundaries share the a-pair as well.
            #pragma unroll
            for (int j = 0; j < 4; j++) {
                float2 blo = make_float2(b4[j].x, b4[j].y);
                float2 bhi = make_float2(b4[j].z, b4[j].w);
                if ((j & 1) == 0) {
                    acc[0][2 * j]     = ffma2(ap1, blo, acc[0][2 * j]);
                    acc[0][2 * j + 1] = ffma2(ap1, bhi, acc[0][2 * j + 1]);
                    acc[1][2 * j + 1] = ffma2(ap2, bhi, acc[1][2 * j + 1]);
                    acc[1][2 * j]     = ffma2(ap2, blo, acc[1][2 * j]);
                } else {
                    acc[1][2 * j]     = ffma2(ap2, blo, acc[1][2 * j]);
                    acc[1][2 * j + 1] = ffma2(ap2, bhi, acc[1][2 * j + 1]);
                    acc[0][2 * j + 1] = ffma2(ap1, bhi, acc[0][2 * j + 1]);
                    acc[0][2 * j]     = ffma2(ap1, blo, acc[0][2 * j]);
                }
            }
        }

        if (has_next) {
            #pragma unroll
            for (int i = 0; i < 4; i++) {
                int q = aq[i], col = am[i] ^ (4 * q);
                float vs[4] = {pa[i].x, pa[i].y, pa[i].z, pa[i].w};
                #pragma unroll
                for (int j = 0; j < 4; j++)
                    a_nx[(4 * q + j) * BM + col] = vs[j];
            }
            cp_async_wait0();
        }
        __syncthreads();
    }

    // ---- epilogue: logits to global + stage rows in smem for topk ----
    #pragma unroll
    for (int r = 0; r < 2; r++) {
        int m = r ? m2 : m1;
        #pragma unroll
        for (int j = 0; j < 4; j++) {
            float4 v = make_float4(acc[r][2 * j].x, acc[r][2 * j].y,
                                   acc[r][2 * j + 1].x, acc[r][2 * j + 1].y);
            *reinterpret_cast<float4*>(&logits[(size_t)(m0 + m) * E_DIM + e0 + 4 * j]) = v;
            *reinterpret_cast<float4*>(&smem[m * LSTR + e0 + 4 * j]) = v;
        }
    }
    __syncthreads();

    // ---- top-8 + softmax: one thread per token (threads 0..127) ----
    if (tid < BM) {
        const float* row = &smem[tid * LSTR];
        float tv[TOPK];
        int   ti[TOPK];
        #pragma unroll
        for (int i = 0; i < TOPK; i++) { tv[i] = -3.4e38f; ti[i] = 0; }

        #pragma unroll
        for (int q = 0; q < E_DIM / 4; q++) {
            float4 v4 = *reinterpret_cast<const float4*>(&row[q * 4]);
            float vs[4] = {v4.x, v4.y, v4.z, v4.w};
            #pragma unroll
            for (int u = 0; u < 4; u++) {
                float v = vs[u];
                int   e = q * 4 + u;
                if (v > tv[TOPK - 1]) {
                    tv[TOPK - 1] = v; ti[TOPK - 1] = e;
                    #pragma unroll
                    for (int j = TOPK - 1; j > 0; j--) {
                        if (tv[j] > tv[j - 1]) {   // strict: ties keep earlier index
                            float tf = tv[j]; tv[j] = tv[j - 1]; tv[j - 1] = tf;
                            int   tx = ti[j]; ti[j] = ti[j - 1]; ti[j - 1] = tx;
                        }
                    }
                }
            }
        }

        float mx = tv[0];
        float ev[TOPK], ssum = 0.f;
        #pragma unroll
        for (int i = 0; i < TOPK; i++) { ev[i] = __expf(tv[i] - mx); ssum += ev[i]; }
        float inv = 1.f / ssum;
        size_t tok = (size_t)(m0 + tid);
        #pragma unroll
        for (int i = 0; i < TOPK; i++) {
            wout[tok * TOPK + i] = ev[i] * inv;
            eout[tok * TOPK + i] = (float)ti[i];
        }
    }
}

extern "C" void kernel_launch(void* const* d_in, const int* in_sizes, int n_in,
                              void* d_out, int out_size) {
    const float* X = (const float*)d_in[0];   // [4,4096,2048] fp32
    const float* W = (const float*)d_in[1];   // [64,2048]     fp32

    float* out    = (float*)d_out;
    float* logits = out;                                   // 16384*64
    float* wts    = out + (size_t)M_TOTAL * E_DIM;         // 16384*8
    float* exps   = wts + (size_t)M_TOTAL * TOPK;          // 16384*8

    float* Wt;
    cudaGetSymbolAddress((void**)&Wt, Wt_g);

    transpose_w<<<(K_DIM * E_DIM) / 256, 256>>>(W, Wt);
    router_fused<<<M_TOTAL / BM, NTHR>>>(X, Wt, logits, wts, exps);
}

// round 11
// speedup vs baseline: 1.5078x; 1.0702x over previous
#include <cuda_runtime.h>
#include <cstdint>

#define M_TOTAL 16384
#define K_DIM   2048
#define E_DIM   64
#define TOPK    8

#define BM    128
#define BK    64
#define NTILE (K_DIM / BK)   // 32
#define NTHR  256
#define LSTR  68             // epilogue logits row stride (floats)
#define BUFSZ (BK * BM + BK * E_DIM)   // 12288 floats per buffer (48 KB)

// One-time W transpose scratch: Wt[k][e]
__device__ float Wt_g[(size_t)K_DIM * E_DIM];

__global__ void transpose_w(const float* __restrict__ W, float* __restrict__ Wt) {
    int t = blockIdx.x * blockDim.x + threadIdx.x;   // 131072
    int e = t >> 11;
    int k = t & (K_DIM - 1);
    Wt[(size_t)k * E_DIM + e] = W[(size_t)e * K_DIM + k];
}

// Packed fp32x2 FMA; per-lane rounding identical to scalar fmaf.
__device__ __forceinline__ float2 ffma2(float2 a, float2 b, float2 c) {
    float2 d;
    asm("fma.rn.f32x2 %0, %1, %2, %3;"
        : "=l"(reinterpret_cast<unsigned long long&>(d))
        : "l"(reinterpret_cast<unsigned long long&>(a)),
          "l"(reinterpret_cast<unsigned long long&>(b)),
          "l"(reinterpret_cast<unsigned long long&>(c)));
    return d;
}

__device__ __forceinline__ void cp_async16(uint32_t dst_smem, const void* src) {
    asm volatile("cp.async.ca.shared.global [%0], [%1], 16;"
                 :: "r"(dst_smem), "l"(src));
}
__device__ __forceinline__ void cp_async_commit() {
    asm volatile("cp.async.commit_group;");
}
__device__ __forceinline__ void cp_async_wait0() {
    asm volatile("cp.async.wait_group 0;");
}

// Fused logits GEMM + top-8 + softmax. Round-8 structure scaled to BK=64
// (dynamic 96 KB smem, 32 tiles -> half the barriers / per-tile overhead).
// Warp = 16 experts x 2 m-rows; uniform LDS.128 b, coalesced LDS.32 a with
// XOR swizzle col = m ^ (4*(k>>2)). a-prefetch in two 4xfloat4 batches to
// keep regs flat. Sequential ascending-k FMA chain per (m,e) -> bit-identical
// outputs to all passing rounds (index exactness is mandatory).
__global__ __launch_bounds__(NTHR, 1)
void router_fused(const float* __restrict__ X, const float* __restrict__ Wt,
                  float* __restrict__ logits,
                  float* __restrict__ wout, float* __restrict__ eout) {
    extern __shared__ float smem[];            // 2 * BUFSZ floats = 96 KB

    const int tid  = threadIdx.x;
    const int w    = tid >> 5;
    const int lane = tid & 31;
    const int e0   = (w & 3) * 16;
    const int m1   = (w >> 2) * 64 + lane;
    const int m2   = m1 + 32;
    const int m0   = blockIdx.x * BM;

    const uint32_t smem_u32 = (uint32_t)__cvta_generic_to_shared(smem);

    float2 acc[2][8];
    #pragma unroll
    for (int r = 0; r < 2; r++)
        #pragma unroll
        for (int j = 0; j < 8; j++) acc[r][j] = make_float2(0.f, 0.f);

    // a-tile: 128 rows x 64 k = 2048 float4 -> 8 per thread, in 2 batches of 4.
    // float4 index f = tid + i*256: row = f>>4 (16 float4 per row), q = f&15.
    int arow[8], aq[8];
    #pragma unroll
    for (int i = 0; i < 8; i++) { int f = tid + i * NTHR; arow[i] = f >> 4; aq[i] = f & 15; }

    // ---- preload tile 0 ----
    {
        // b tile: 64x64 floats = 1024 float4 -> 4 cp.async per thread
        uint32_t b0 = smem_u32 + (uint32_t)(BK * BM) * 4u;
        #pragma unroll
        for (int i = 0; i < 4; i++)
            cp_async16(b0 + (tid + i * NTHR) * 16u, &Wt[(size_t)(tid + i * NTHR) * 4]);
        cp_async_commit();
        // a tile: LDG -> swizzled STS
        #pragma unroll
        for (int i = 0; i < 8; i++) {
            float4 v = *reinterpret_cast<const float4*>(
                &X[(size_t)(m0 + arow[i]) * K_DIM + aq[i] * 4]);
            int q = aq[i], col0 = arow[i] ^ (4 * q);
            float vs[4] = {v.x, v.y, v.z, v.w};
            #pragma unroll
            for (int j = 0; j < 4; j++)
                smem[(4 * q + j) * BM + col0] = vs[j];
        }
        cp_async_wait0();
    }
    __syncthreads();

    for (int t = 0; t < NTILE; t++) {
        const int cur = t & 1;
        const float* a_sm = smem + cur * BUFSZ;
        const float* b_sm = a_sm + BK * BM;
        float* a_nx = smem + (cur ^ 1) * BUFSZ;

        const bool has_next = (t + 1 < NTILE);
        float4 pa[4];

        // issue next-tile b (cp.async) + first a batch (LDG)
        if (has_next) {
            int kn = (t + 1) * BK;
            uint32_t bdst = smem_u32 + (uint32_t)((cur ^ 1) * BUFSZ + BK * BM) * 4u;
            const float* bsrc = &Wt[(size_t)kn * E_DIM];
            #pragma unroll
            for (int i = 0; i < 4; i++)
                cp_async16(bdst + (tid + i * NTHR) * 16u, bsrc + (size_t)(tid + i * NTHR) * 4);
            cp_async_commit();
            #pragma unroll
            for (int i = 0; i < 4; i++)
                pa[i] = *reinterpret_cast<const float4*>(
                    &X[(size_t)(m0 + arow[i]) * K_DIM + kn + aq[i] * 4]);
        }

        // ---- first half of mainloop ----
        #pragma unroll
        for (int kk = 0; kk < BK / 2; kk++) {
            const int sw = 4 * (kk >> 2);
            float4 b4[4];
            #pragma unroll
            for (int j = 0; j < 4; j++)
                b4[j] = *reinterpret_cast<const float4*>(&b_sm[kk * E_DIM + e0 + 4 * j]);
            float a1 = a_sm[kk * BM + (m1 ^ sw)];
            float a2 = a_sm[kk * BM + (m2 ^ sw)];
            float2 ap1 = make_float2(a1, a1);
            float2 ap2 = make_float2(a2, a2);
            #pragma unroll
            for (int j = 0; j < 4; j++) {
                float2 blo = make_float2(b4[j].x, b4[j].y);
                float2 bhi = make_float2(b4[j].z, b4[j].w);
                acc[0][2 * j]     = ffma2(ap1, blo, acc[0][2 * j]);
                acc[0][2 * j + 1] = ffma2(ap1, bhi, acc[0][2 * j + 1]);
                acc[1][2 * j]     = ffma2(ap2, blo, acc[1][2 * j]);
                acc[1][2 * j + 1] = ffma2(ap2, bhi, acc[1][2 * j + 1]);
            }
        }

        // store a batch 1, issue a batch 2
        if (has_next) {
            int kn = (t + 1) * BK;
            #pragma unroll
            for (int i = 0; i < 4; i++) {
                int q = aq[i], col0 = arow[i] ^ (4 * q);
                float vs[4] = {pa[i].x, pa[i].y, pa[i].z, pa[i].w};
                #pragma unroll
                for (int j = 0; j < 4; j++)
                    a_nx[(4 * q + j) * BM + col0] = vs[j];
            }
            #pragma unroll
            for (int i = 0; i < 4; i++)
                pa[i] = *reinterpret_cast<const float4*>(
                    &X[(size_t)(m0 + arow[i + 4]) * K_DIM + kn + aq[i + 4] * 4]);
        }

        // ---- second half of mainloop ----
        #pragma unroll
        for (int kk = BK / 2; kk < BK; kk++) {
            const int sw = 4 * (kk >> 2);
            float4 b4[4];
            #pragma unroll
            for (int j = 0; j < 4; j++)
                b4[j] = *reinterpret_cast<const float4*>(&b_sm[kk * E_DIM + e0 + 4 * j]);
            float a1 = a_sm[kk * BM + (m1 ^ sw)];
            float a2 = a_sm[kk * BM + (m2 ^ sw)];
            float2 ap1 = make_float2(a1, a1);
            float2 ap2 = make_float2(a2, a2);
            #pragma unroll
            for (int j = 0; j < 4; j++) {
                float2 blo = make_float2(b4[j].x, b4[j].y);
                float2 bhi = make_float2(b4[j].z, b4[j].w);
                acc[0][2 * j]     = ffma2(ap1, blo, acc[0][2 * j]);
                acc[0][2 * j + 1] = ffma2(ap1, bhi, acc[0][2 * j + 1]);
                acc[1][2 * j]     = ffma2(ap2, blo, acc[1][2 * j]);
                acc[1][2 * j + 1] = ffma2(ap2, bhi, acc[1][2 * j + 1]);
            }
        }

        // store a batch 2, wait for b
        if (has_next) {
            #pragma unroll
            for (int i = 0; i < 4; i++) {
                int q = aq[i + 4], col0 = arow[i + 4] ^ (4 * q);
                float vs[4] = {pa[i].x, pa[i].y, pa[i].z, pa[i].w};
                #pragma unroll
                for (int j = 0; j < 4; j++)
                    a_nx[(4 * q + j) * BM + col0] = vs[j];
            }
            cp_async_wait0();
        }
        __syncthreads();
    }

    // ---- epilogue: logits to global + stage rows in smem for topk ----
    #pragma unroll
    for (int r = 0; r < 2; r++) {
        int m = r ? m2 : m1;
        #pragma unroll
        for (int j = 0; j < 4; j++) {
            float4 v = make_float4(acc[r][2 * j].x, acc[r][2 * j].y,
                                   acc[r][2 * j + 1].x, acc[r][2 * j + 1].y);
            *reinterpret_cast<float4*>(&logits[(size_t)(m0 + m) * E_DIM + e0 + 4 * j]) = v;
            *reinterpret_cast<float4*>(&smem[m * LSTR + e0 + 4 * j]) = v;
        }
    }
    __syncthreads();

    // ---- top-8 + softmax: one thread per token (threads 0..127) ----
    if (tid < BM) {
        const float* row = &smem[tid * LSTR];
        float tv[TOPK];
        int   ti[TOPK];
        #pragma unroll
        for (int i = 0; i < TOPK; i++) { tv[i] = -3.4e38f; ti[i] = 0; }

        #pragma unroll
        for (int q = 0; q < E_DIM / 4; q++) {
            float4 v4 = *reinterpret_cast<const float4*>(&row[q * 4]);
            float vs[4] = {v4.x, v4.y, v4.z, v4.w};
            #pragma unroll
            for (int u = 0; u < 4; u++) {
                float v = vs[u];
                int   e = q * 4 + u;
                if (v > tv[TOPK - 1]) {
                    tv[TOPK - 1] = v; ti[TOPK - 1] = e;
                    #pragma unroll
                    for (int j = TOPK - 1; j > 0; j--) {
                        if (tv[j] > tv[j - 1]) {   // strict: ties keep earlier index
                            float tf = tv[j]; tv[j] = tv[j - 1]; tv[j - 1] = tf;
                            int   tx = ti[j]; ti[j] = ti[j - 1]; ti[j - 1] = tx;
                        }
                    }
                }
            }
        }

        float mx = tv[0];
        float ev[TOPK], ssum = 0.f;
        #pragma unroll
        for (int i = 0; i < TOPK; i++) { ev[i] = __expf(tv[i] - mx); ssum += ev[i]; }
        float inv = 1.f / ssum;
        size_t tok = (size_t)(m0 + tid);
        #pragma unroll
        for (int i = 0; i < TOPK; i++) {
            wout[tok * TOPK + i] = ev[i] * inv;
            eout[tok * TOPK + i] = (float)ti[i];
        }
    }
}

extern "C" void kernel_launch(void* const* d_in, const int* in_sizes, int n_in,
                              void* d_out, int out_size) {
    const float* X = (const float*)d_in[0];   // [4,4096,2048] fp32
    const float* W = (const float*)d_in[1];   // [64,2048]     fp32

    float* out    = (float*)d_out;
    float* logits = out;                                   // 16384*64
    float* wts    = out + (size_t)M_TOTAL * E_DIM;         // 16384*8
    float* exps   = wts + (size_t)M_TOTAL * TOPK;          // 16384*8

    float* Wt;
    cudaGetSymbolAddress((void**)&Wt, Wt_g);

    const int smem_bytes = 2 * BUFSZ * (int)sizeof(float);   // 96 KB
    cudaFuncSetAttribute(router_fused, cudaFuncAttributeMaxDynamicSharedMemorySize,
                         smem_bytes);

    transpose_w<<<(K_DIM * E_DIM) / 256, 256>>>(W, Wt);
    router_fused<<<M_TOTAL / BM, NTHR, smem_bytes>>>(X, Wt, logits, wts, exps);
}